// round 13
// baseline (speedup 1.0000x reference)
#include <cuda_runtime.h>
#include <cuda_bf16.h>
#include <cuda_fp16.h>
#include <cstdint>
#include <cstddef>

// Problem sizes (fixed by the reference)
constexpr int M  = 8192;    // batch
constexpr int N  = 16384;   // d_sae
constexpr int KD = 1024;    // d_in
constexpr int TOPK = 32;
constexpr int NCAND = 48;   // candidate pool for exact refinement
constexpr float TAU = 4e-3f;  // boundary gap threshold (fp16 scan noise)

// Output layout: [x_hat (M*KD), h_sparse (M*N), recon_loss, l0]
constexpr size_t OFF_H    = (size_t)M * KD;
constexpr size_t OFF_LOSS = OFF_H + (size_t)M * N;

// Scratch: control state + transposed W copies (96 MB total; proven-safe regime)
__device__ float g_val[M * TOPK];
__device__ int   g_idx[M * TOPK];
__device__ float g_loss_sum;
__device__ int   g_pos_count;
__device__ int   g_w0_is_enc;
__device__ __align__(16) __half g_wt_f16[(size_t)N * KD];   // 32 MB, W_enc^T [N][KD]
__device__ __align__(16) float  g_wt_f32[(size_t)N * KD];   // 64 MB, W_enc^T [N][KD]

// ---------------------------------------------------------------------------
// Helpers (sm_80-compatible PTX only: mma.sync + cp.async + ldmatrix)
// ---------------------------------------------------------------------------
__device__ __forceinline__ void mma_fp16(float* c, const uint32_t* a, const uint32_t* b) {
    asm volatile(
        "mma.sync.aligned.m16n8k16.row.col.f32.f16.f16.f32 "
        "{%0,%1,%2,%3}, {%4,%5,%6,%7}, {%8,%9}, {%0,%1,%2,%3};\n"
        : "+f"(c[0]), "+f"(c[1]), "+f"(c[2]), "+f"(c[3])
        : "r"(a[0]), "r"(a[1]), "r"(a[2]), "r"(a[3]), "r"(b[0]), "r"(b[1]));
}
__device__ __forceinline__ void cp_async16(uint32_t saddr, const void* gptr) {
    asm volatile("cp.async.ca.shared.global [%0], [%1], 16;" :: "r"(saddr), "l"(gptr));
}
#define CP_COMMIT()  asm volatile("cp.async.commit_group;" ::: "memory")
#define CP_WAIT(n)   asm volatile("cp.async.wait_group %0;" :: "n"(n) : "memory")
__device__ __forceinline__ void ldmx4(uint32_t* r, uint32_t addr) {
    asm volatile("ldmatrix.sync.aligned.m8n8.x4.shared.b16 {%0,%1,%2,%3}, [%4];"
        : "=r"(r[0]), "=r"(r[1]), "=r"(r[2]), "=r"(r[3]) : "r"(addr));
}

// ---------------------------------------------------------------------------
// Kernel D: decide which 16.7M tensor is W_enc; reset accumulators.
// ---------------------------------------------------------------------------
__global__ void detect_kernel(const float* __restrict__ w0,
                              const float* __restrict__ w1) {
    __shared__ float s0[256], s1[256];
    const int tid = threadIdx.x;
    float m0 = 0.f, m1 = 0.f;
    for (int i = tid; i < 8192; i += 256) {
        m0 = fmaxf(m0, fabsf(w0[i]));
        m1 = fmaxf(m1, fabsf(w1[i]));
    }
    s0[tid] = m0; s1[tid] = m1;
    __syncthreads();
    #pragma unroll
    for (int s = 128; s > 0; s >>= 1) {
        if (tid < s) {
            s0[tid] = fmaxf(s0[tid], s0[tid + s]);
            s1[tid] = fmaxf(s1[tid], s1[tid + s]);
        }
        __syncthreads();
    }
    if (tid == 0) {
        g_w0_is_enc = (s0[0] > s1[0]) ? 1 : 0;
        g_loss_sum  = 0.f;
        g_pos_count = 0;
    }
}

// ---------------------------------------------------------------------------
// Kernel C1: x fp32 -> fp16, stored in the x_hat region of d_out.
// ---------------------------------------------------------------------------
__global__ void convert_x_kernel(const float* __restrict__ x,
                                 __half* __restrict__ xh) {
    const size_t i = ((size_t)blockIdx.x * 256 + threadIdx.x) * 8;
    float4 v0 = *(const float4*)(x + i);
    float4 v1 = *(const float4*)(x + i + 4);
    __half2 h[4];
    h[0] = __floats2half2_rn(v0.x, v0.y);
    h[1] = __floats2half2_rn(v0.z, v0.w);
    h[2] = __floats2half2_rn(v1.x, v1.y);
    h[3] = __floats2half2_rn(v1.z, v1.w);
    *(uint4*)(xh + i) = *(uint4*)h;
}

// ---------------------------------------------------------------------------
// Kernel C2: transpose W_enc [KD][N] -> g_wt_f16 and g_wt_f32 [N][KD].
// ---------------------------------------------------------------------------
__global__ void convert_w_kernel(const float* __restrict__ W0,
                                 const float* __restrict__ W1) {
    __shared__ float tile[32][33];
    const float* __restrict__ W = g_w0_is_enc ? W0 : W1;   // W_enc [KD][N]
    const int n0 = blockIdx.x * 32;
    const int k0 = blockIdx.y * 32;
    const int tx = threadIdx.x & 31;
    const int ty = threadIdx.x >> 5;     // 0..7
    #pragma unroll
    for (int i = 0; i < 4; i++) {
        const int kr = ty + i * 8;
        tile[kr][tx] = W[(size_t)(k0 + kr) * N + n0 + tx];
    }
    __syncthreads();
    #pragma unroll
    for (int i = 0; i < 4; i++) {
        const int nr = ty + i * 8;
        const float f = tile[tx][nr];
        g_wt_f16[(size_t)(n0 + nr) * KD + k0 + tx] = __float2half_rn(f);
        g_wt_f32[(size_t)(n0 + nr) * KD + k0 + tx] = f;
    }
}

// ---------------------------------------------------------------------------
// Kernel 1: encoder GEMM, single-pass fp16 HMMA, fp32 accumulate.
// CTA 128(M) x 256(N), 8 warps (2x4), warp tile 64x64, k16 chunks,
// 2-stage cp.async, one __syncthreads per chunk.
// Geometry change vs R12: smem fragment traffic drops 250 -> 172 B/HMMA
// (the profiled bottleneck: L1 was 89.7%).
// SMEM: (128+256) rows x 48B x 2 buffers = 36 KB static.
// ---------------------------------------------------------------------------
constexpr uint32_t SOFF_A = 0, SOFF_B = 6144;
constexpr uint32_t BUFSZ = 18432;

__global__ void __launch_bounds__(256, 1) enc_gemm_hmma(
    const __half* __restrict__ xh,   // [M][KD]
    const float* __restrict__ be,
    float* __restrict__ C)
{
    __shared__ __align__(16) uint8_t smraw[2 * BUFSZ];   // 36 KB static

    const int tid  = threadIdx.x;
    const int warp = tid >> 5;
    const int lane = tid & 31;
    const int g    = lane >> 2;
    const int t    = lane & 3;
    const int wm   = warp >> 2;      // 0..1 -> M 64-half
    const int wn   = warp & 3;       // 0..3 -> N 64-quarter
    const int rowBase = blockIdx.y * 128;
    const int colBase = blockIdx.x * 256;
    const uint32_t sb = (uint32_t)__cvta_generic_to_shared(smraw);

    // cp.async: A 256 transfers (1/thread), B 512 transfers (2/thread)
    const int ldrow = tid >> 1;
    const int ldseg = tid & 1;
    const uint32_t dstOffA  = (uint32_t)ldrow * 48 + (uint32_t)ldseg * 16;
    const uint32_t dstOffB0 = dstOffA;
    const uint32_t dstOffB1 = (uint32_t)(ldrow + 128) * 48 + (uint32_t)ldseg * 16;
    const size_t aSrc  = (size_t)(rowBase + ldrow) * KD + ldseg * 8;
    const size_t bSrc0 = (size_t)(colBase + ldrow) * KD + ldseg * 8;
    const size_t bSrc1 = (size_t)(colBase + 128 + ldrow) * KD + ldseg * 8;

    // ldmatrix per-lane base offsets (row*48 + (lane>=16)*16)
    const uint32_t aFragOff = (uint32_t)(wm * 64 + (lane & 15)) * 48 + ((lane >> 4) * 16);
    const uint32_t bFragOff = (uint32_t)(wn * 64 + (lane & 15)) * 48 + ((lane >> 4) * 16);

    float acc[4][8][4];
    #pragma unroll
    for (int i = 0; i < 4; i++)
        #pragma unroll
        for (int j = 0; j < 8; j++)
            #pragma unroll
            for (int e = 0; e < 4; e++) acc[i][j][e] = 0.f;

    auto issue = [&](int k0, int buf) {
        const uint32_t b = sb + (uint32_t)buf * BUFSZ;
        cp_async16(b + SOFF_A + dstOffA,  xh + aSrc + k0);
        cp_async16(b + SOFF_B + dstOffB0, g_wt_f16 + bSrc0 + k0);
        cp_async16(b + SOFF_B + dstOffB1, g_wt_f16 + bSrc1 + k0);
        CP_COMMIT();
    };

    issue(0, 0);
    #pragma unroll 1
    for (int ic = 0; ic < KD / 16; ic++) {
        CP_WAIT(0);            // chunk ic resident in buffer ic&1
        __syncthreads();       // all warps done with buffer (ic+1)&1 (computed at ic-1)
        if (ic < KD / 16 - 1)
            issue((ic + 1) * 16, (ic + 1) & 1);   // fills (ic+1)&1 while we compute

        const uint32_t bb = sb + (uint32_t)(ic & 1) * BUFSZ;
        uint32_t ah[4][4], bh[4][4];
        #pragma unroll
        for (int mf = 0; mf < 4; mf++)
            ldmx4(ah[mf], bb + SOFF_A + aFragOff + mf * 768);
        #pragma unroll
        for (int b4 = 0; b4 < 4; b4++)
            ldmx4(bh[b4], bb + SOFF_B + bFragOff + b4 * 768);

        #pragma unroll
        for (int mf = 0; mf < 4; mf++) {
            #pragma unroll
            for (int b4 = 0; b4 < 4; b4++) {
                uint32_t b0[2] = { bh[b4][0], bh[b4][2] };
                uint32_t b1[2] = { bh[b4][1], bh[b4][3] };
                mma_fp16(acc[mf][2 * b4 + 0], ah[mf], b0);
                mma_fp16(acc[mf][2 * b4 + 1], ah[mf], b1);
            }
        }
        // no trailing sync: next iteration's top sync covers the hazard
    }

    // Epilogue: bias + relu + store
    #pragma unroll
    for (int mf = 0; mf < 4; mf++) {
        const int row = rowBase + wm * 64 + mf * 16 + g;
        #pragma unroll
        for (int b4 = 0; b4 < 4; b4++) {
            #pragma unroll
            for (int j = 0; j < 2; j++) {
                const int col = colBase + wn * 64 + b4 * 16 + j * 8 + 2 * t;
                const float* a = acc[mf][2 * b4 + j];
                const float2 bv = *(const float2*)(be + col);
                float2 o0, o1;
                o0.x = fmaxf(a[0] + bv.x, 0.f);
                o0.y = fmaxf(a[1] + bv.y, 0.f);
                o1.x = fmaxf(a[2] + bv.x, 0.f);
                o1.y = fmaxf(a[3] + bv.y, 0.f);
                *(float2*)(C + (size_t)row * N + col)       = o0;
                *(float2*)(C + (size_t)(row + 8) * N + col) = o1;
            }
        }
    }
}

// ---------------------------------------------------------------------------
// Kernel 2: per-row top-32 with exact fp64 refinement, warp-per-row.
// (unchanged from the passing R12 kernel)
// ---------------------------------------------------------------------------
__global__ __launch_bounds__(256) void topk_kernel(
    float* __restrict__ hsp,
    const float* __restrict__ x,
    const float* __restrict__ be)
{
    __shared__ float  s_cv[8][NCAND];
    __shared__ int    s_ci[8][NCAND];
    __shared__ double s_rv[8][NCAND];
    __shared__ int    s_keep[8][TOPK];

    const int w    = threadIdx.x >> 5;
    const int lane = threadIdx.x & 31;
    const int row  = blockIdx.x * 8 + w;
    float* pre = hsp + (size_t)row * N;

    float mv = -1.f; int mi = 1 << 30;
    #pragma unroll 4
    for (int j = 0; j < 128; j++) {
        int gi = (j * 32 + lane) * 4;
        float4 v = *(const float4*)(pre + gi);
        if (v.x > mv) { mv = v.x; mi = gi; }
        if (v.y > mv) { mv = v.y; mi = gi + 1; }
        if (v.z > mv) { mv = v.z; mi = gi + 2; }
        if (v.w > mv) { mv = v.w; mi = gi + 3; }
    }

    for (int it = 0; it < NCAND; it++) {
        float bv = mv; int bi = mi;
        #pragma unroll
        for (int s = 16; s; s >>= 1) {
            float ov = __shfl_xor_sync(0xffffffffu, bv, s);
            int   oi = __shfl_xor_sync(0xffffffffu, bi, s);
            if (ov > bv || (ov == bv && oi < bi)) { bv = ov; bi = oi; }
        }
        if (lane == 0) {
            s_cv[w][it] = bv;
            s_ci[w][it] = bi;
            pre[bi] = -2.f;
        }
        __syncwarp();

        if (it < NCAND - 1) {
            const int wl = (bi >> 2) & 31;
            float nmv = -1.f; int nmi = 1 << 30;
            #pragma unroll
            for (int q = 0; q < 4; q++) {
                int j  = lane * 4 + q;
                int gi = (j * 32 + wl) * 4;
                float4 v = *(const float4*)(pre + gi);
                if (v.x > nmv) { nmv = v.x; nmi = gi; }
                if (v.y > nmv) { nmv = v.y; nmi = gi + 1; }
                if (v.z > nmv) { nmv = v.z; nmi = gi + 2; }
                if (v.w > nmv) { nmv = v.w; nmi = gi + 3; }
            }
            #pragma unroll
            for (int s = 16; s; s >>= 1) {
                float ov = __shfl_xor_sync(0xffffffffu, nmv, s);
                int   oi = __shfl_xor_sync(0xffffffffu, nmi, s);
                if (ov > nmv || (ov == nmv && oi < nmi)) { nmv = ov; nmi = oi; }
            }
            if (lane == wl) { mv = nmv; mi = nmi; }
        }
    }
    __syncwarp();

    const float gap = s_cv[w][TOPK - 1] - s_cv[w][TOPK];
    if (gap < TAU) {
        // fp64 refinement; reads transposed fp32 W contiguously per candidate.
        const float* xr = x + (size_t)row * KD;
        for (int c = 0; c < NCAND; c++) {
            const int idx = s_ci[w][c];
            const float* wr = g_wt_f32 + (size_t)idx * KD;
            double s = 0.0;
            for (int k = lane; k < KD; k += 32)
                s += (double)xr[k] * (double)wr[k];
            #pragma unroll
            for (int sh = 16; sh; sh >>= 1)
                s += __shfl_xor_sync(0xffffffffu, s, sh);
            if (lane == 0) s_rv[w][c] = s + (double)be[idx];
        }
        __syncwarp();
        if (lane == 0) {
            int cnt = 0;
            for (int c = 0; c < NCAND && cnt < TOPK; c++) {
                int rank = 0;
                const double vc = s_rv[w][c];
                const int ic = s_ci[w][c];
                for (int d = 0; d < NCAND; d++) {
                    const double vd = s_rv[w][d];
                    if (vd > vc || (vd == vc && s_ci[w][d] < ic)) rank++;
                }
                if (rank < TOPK) s_keep[w][cnt++] = c;
            }
            for (; cnt < TOPK; cnt++) s_keep[w][cnt] = cnt;
        }
    } else if (lane == 0) {
        #pragma unroll
        for (int i = 0; i < TOPK; i++) s_keep[w][i] = i;
    }
    __syncwarp();

    const float4 z4 = make_float4(0.f, 0.f, 0.f, 0.f);
    #pragma unroll 4
    for (int j = 0; j < 128; j++) {
        int gi = (j * 32 + lane) * 4;
        *(float4*)(pre + gi) = z4;
    }
    __syncwarp();
    if (lane == 0) {
        int pos = 0;
        #pragma unroll
        for (int i = 0; i < TOPK; i++) {
            const int c = s_keep[w][i];
            const float v = s_cv[w][c];
            const int idx = s_ci[w][c];
            pre[idx] = v;
            g_val[row * TOPK + i] = v;
            g_idx[row * TOPK + i] = idx;
            if (v > 0.f) pos++;
        }
        atomicAdd(&g_pos_count, pos);
    }
}

// ---------------------------------------------------------------------------
// Kernel 3: sparse decoder + squared-error accumulation (unchanged)
// ---------------------------------------------------------------------------
__global__ __launch_bounds__(256) void decoder_kernel(
    const float* __restrict__ x,
    const float* __restrict__ W0,
    const float* __restrict__ W1,
    const float* __restrict__ bd,
    float* __restrict__ xhat)
{
    const float* __restrict__ Wd = g_w0_is_enc ? W1 : W0;   // W_dec [N, KD]

    __shared__ float sv[TOPK];
    __shared__ int   si[TOPK];
    __shared__ float red[256];

    const int row = blockIdx.x;
    const int tid = threadIdx.x;
    if (tid < TOPK) {
        sv[tid] = g_val[row * TOPK + tid];
        si[tid] = g_idx[row * TOPK + tid];
    }
    __syncthreads();

    const int d = tid * 4;
    float4 acc = *(const float4*)(bd + d);
    #pragma unroll 4
    for (int j = 0; j < TOPK; j++) {
        float v = sv[j];
        float4 wv = *(const float4*)(Wd + (size_t)si[j] * KD + d);
        acc.x = fmaf(v, wv.x, acc.x);
        acc.y = fmaf(v, wv.y, acc.y);
        acc.z = fmaf(v, wv.z, acc.z);
        acc.w = fmaf(v, wv.w, acc.w);
    }
    *(float4*)(xhat + (size_t)row * KD + d) = acc;

    float4 xv = *(const float4*)(x + (size_t)row * KD + d);
    float ex = acc.x - xv.x, ey = acc.y - xv.y;
    float ez = acc.z - xv.z, ew = acc.w - xv.w;
    red[tid] = ex * ex + ey * ey + ez * ez + ew * ew;
    __syncthreads();
    #pragma unroll
    for (int s = 128; s > 0; s >>= 1) {
        if (tid < s) red[tid] += red[tid + s];
        __syncthreads();
    }
    if (tid == 0) atomicAdd(&g_loss_sum, red[0]);
}

// ---------------------------------------------------------------------------
// Kernel 4: finalize scalars
// ---------------------------------------------------------------------------
__global__ void finalize_kernel(float* __restrict__ scal) {
    scal[0] = g_loss_sum / (float)((size_t)M * KD);
    scal[1] = (float)g_pos_count / (float)M;
}

// ---------------------------------------------------------------------------
extern "C" void kernel_launch(void* const* d_in, const int* in_sizes, int n_in,
                              void* d_out, int out_size) {
    const float* x  = nullptr;
    const float* be = nullptr;
    const float* bd = nullptr;
    const float* w0 = nullptr;
    const float* w1 = nullptr;
    for (int i = 0; i < n_in; i++) {
        const float* p = (const float*)d_in[i];
        const long long s = in_sizes[i];
        if      (s == (long long)M * KD || s == (long long)M * KD * 4) x  = p;
        else if (s == N        || s == (long long)N * 4)               be = p;
        else if (s == KD       || s == (long long)KD * 4)              bd = p;
        else if (s == (long long)KD * N || s == (long long)KD * N * 4) { if (!w0) w0 = p; else w1 = p; }
    }
    if (!x || !be || !bd || !w0 || !w1) {
        x  = (const float*)d_in[0];
        w0 = (const float*)d_in[1];
        be = (const float*)d_in[2];
        w1 = (const float*)d_in[3];
        bd = (const float*)d_in[4];
    }

    float* out  = (float*)d_out;
    float* xhat = out;
    float* hsp  = out + OFF_H;
    float* scal = out + OFF_LOSS;

    // x_f16 lives in the x_hat region until the decoder overwrites it
    __half* xh = (__half*)xhat;

    detect_kernel<<<1, 256>>>(w0, w1);

    convert_x_kernel<<<M * KD / 2048, 256>>>(x, xh);
    convert_w_kernel<<<dim3(N / 32, KD / 32), 256>>>(w0, w1);

    dim3 gGrid(N / 256, M / 128);   // (64, 64)
    enc_gemm_hmma<<<gGrid, 256>>>(xh, be, hsp);

    topk_kernel<<<M / 8, 256>>>(hsp, x, be);

    decoder_kernel<<<M, 256>>>(x, w0, w1, bd, xhat);

    finalize_kernel<<<1, 1>>>(scal);
}